// round 14
// baseline (speedup 1.0000x reference)
#include <cuda_runtime.h>
#include <cuda_bf16.h>
#include <math.h>
#include <stdint.h>

#define S_LEN 2048
#define DH    64
#define NB    2
#define NH    8
#define WIN   128
#define TQ    32
#define NT    512
#define KW    320
#define SK    80     // K/Q smem row stride (u32); LDS.128 conflict-free
#define SV    336    // Vt smem row stride (u32)
#define VROW  2208   // Vt gmem row stride (u32)
#define ST    324    // p staging row stride (u32): ≡4 mod 32 banks

// u32 smem offsets
#define O_K    0       // K tile 320*80 = 25600 (Vt overlay 21504; slots + staging later)
#define O_Q    25600   // Q tile 32*80 = 2560
#define O_MS   28160   // f32 [8][32]
#define O_SS   28416
#define O_STG  14336   // p staging [32][324] = 10368, ends 24704 (over dead Vt/K)
#define SM_U32 28672
#define SMEM_B (SM_U32 * 4)   // 114688 B -> 2 CTAs/SM

#define PERM(p) ((((p) & 3) << 1) | ((p) >> 2))
#define FI(f)   ((f) < 0 ? 0 : ((f) > 4 ? 4 : (f)))

// pre-converted tiles (static zero-init; ~17 MB)
__device__ uint32_t d_Kp[NB * NH * S_LEN * 64];
__device__ uint32_t d_Vt[NB * NH * DH * VROW];

__device__ __forceinline__ uint32_t pk(float x, float y) {
    __nv_bfloat162 h = __floats2bfloat162_rn(x, y);
    return *(uint32_t*)&h;
}
__device__ __forceinline__ uint32_t pkres(float x, float y, uint32_t h) {
    __nv_bfloat162 hh = *(__nv_bfloat162*)&h;
    return pk(x - __bfloat162float(hh.x), y - __bfloat162float(hh.y));
}
__device__ __forceinline__ void mmabf(float4& c, uint32_t a0, uint32_t a1, uint32_t a2,
                                      uint32_t a3, uint32_t b0, uint32_t b1) {
    asm("mma.sync.aligned.m16n8k16.row.col.f32.bf16.bf16.f32 "
        "{%0,%1,%2,%3}, {%4,%5,%6,%7}, {%8,%9}, {%0,%1,%2,%3};"
        : "+f"(c.x), "+f"(c.y), "+f"(c.z), "+f"(c.w)
        : "r"(a0), "r"(a1), "r"(a2), "r"(a3), "r"(b0), "r"(b1));
}

// ---- prep: convert K and V once, hi/lo interleaved final layouts ----
__global__ void __launch_bounds__(256)
prep_kernel(const float* __restrict__ K, const float* __restrict__ V)
{
    int idx = blockIdx.x * blockDim.x + threadIdx.x;     // 524288
    {   // K rows
        int dq = idx & 15, r = (idx >> 4) & (S_LEN - 1), bh = idx >> 15;
        int ks = dq >> 2;
        int p0 = PERM((2 * dq) & 7), p1 = PERM((2 * dq + 1) & 7);
        size_t rowi = (size_t)(bh * S_LEN + r);
        float4 kv = ((const float4*)K)[rowi * 16 + dq];
        uint32_t* kr = d_Kp + rowi * 64;
        uint32_t h0 = pk(kv.x, kv.y), h1 = pk(kv.z, kv.w);
        int o0 = ks * 16 + ((p0 >> 1) << 2) + (p0 & 1);
        int o1 = ks * 16 + ((p1 >> 1) << 2) + (p1 & 1);
        kr[o0] = h0; kr[o0 + 2] = pkres(kv.x, kv.y, h0);
        kr[o1] = h1; kr[o1 + 2] = pkres(kv.z, kv.w, h1);
    }
    if (idx < NB * NH * 16 * 1024) {   // V transpose
        int kp = idx & 1023, dq = (idx >> 10) & 15, bh = idx >> 14;
        float4 v0 = ((const float4*)V)[((size_t)(bh * S_LEN) + 2 * kp) * 16 + dq];
        float4 v1 = ((const float4*)V)[((size_t)(bh * S_LEN) + 2 * kp + 1) * 16 + dq];
        int ch = kp >> 3, uu = PERM(kp & 7);
        #pragma unroll
        for (int j = 0; j < 4; ++j) {
            float x0 = (j == 0) ? v0.x : (j == 1) ? v0.y : (j == 2) ? v0.z : v0.w;
            float x1 = (j == 0) ? v1.x : (j == 1) ? v1.y : (j == 2) ? v1.z : v1.w;
            int d = 4 * dq + j;
            int e = uu ^ (((d >> 2) & 3) << 1);
            uint32_t o = (uint32_t)(bh * DH + d) * VROW + ch * 16 + ((e >> 1) << 2) + (e & 1);
            uint32_t h = pk(x0, x1);
            d_Vt[o] = h;
            d_Vt[o + 2] = pkres(x0, x1, h);
        }
    }
}

// GEMM2 k16 step (A = P frags; FA/FB outside [0,4] -> zeros)
#define G2STEP(FA, FB, C2) do {                                                   \
    int ck = chunk0 + (C2);                                                       \
    if (ck * 16 + 15 >= glo && ck * 16 <= ghi) {                                  \
        uint32_t ah0, ah1, ah2, ah3, al0, al1, al2, al3;                          \
        if ((FA) >= 0) {                                                          \
            float4 pa = C[FI(FA)];                                                \
            ah0 = pk(pa.x, pa.y); al0 = pkres(pa.x, pa.y, ah0);                   \
            ah1 = pk(pa.z, pa.w); al1 = pkres(pa.z, pa.w, ah1);                   \
        } else { ah0 = ah1 = al0 = al1 = 0u; }                                    \
        if ((FB) <= 4) {                                                          \
            float4 pb = C[FI(FB)];                                                \
            ah2 = pk(pb.x, pb.y); al2 = pkres(pb.x, pb.y, ah2);                   \
            ah3 = pk(pb.z, pb.w); al3 = pkres(pb.z, pb.w, ah3);                   \
        } else { ah2 = ah3 = al2 = al3 = 0u; }                                    \
        _Pragma("unroll")                                                         \
        for (int nt = 0; nt < 8; ++nt) {                                          \
            uint32_t dr = nt * 8 + gid;                                           \
            uint32_t bi = dr * SV + ck * 16 + ((tig ^ ((dr >> 2) & 3u)) << 2);    \
            uint4 bv = *(const uint4*)(su + bi);                                  \
            mmabf(acc[nt], ah0, ah1, ah2, ah3, bv.x, bv.y);                       \
            mmabf(acc[nt], al0, al1, al2, al3, bv.x, bv.y);                       \
            mmabf(acc[nt], ah0, ah1, ah2, ah3, bv.z, bv.w);                       \
        }                                                                         \
    }                                                                             \
} while (0)

__global__ void __launch_bounds__(NT, 2)
band_attn_bf16(const float* __restrict__ Q, const float* __restrict__ K,
               const float* __restrict__ V, float* __restrict__ ctx_out,
               float* __restrict__ attn_out)
{
    extern __shared__ float smem[];
    uint32_t* su = (uint32_t*)smem;
    float*    sf = smem;

    const int tid = threadIdx.x, w = tid >> 5, lane = tid & 31;
    const int gid = lane >> 2, tig = lane & 3;
    const int m = w >> 3, nw = w & 7;
    const int bh = blockIdx.z * NH + blockIdx.y;
    const int q0 = blockIdx.x * TQ;
    const int klo = max(0, q0 - 128);          // multiple of 32
    const int klo2 = klo >> 1;
    const int khi = min(S_LEN - 1, q0 + TQ - 1 + WIN - 1);
    const int cnt = khi - klo + 1;             // <= 287

    float* attn = attn_out + (size_t)bh * S_LEN * S_LEN;

    // ---- K tile copy ----
    for (int i = tid; i < cnt * 16; i += NT) {
        int r = i >> 4, c = i & 15;
        ((uint4*)(su + O_K + r * SK))[c] =
            ((const uint4*)(d_Kp + ((size_t)(bh * S_LEN) + klo + r) * 64))[c];
    }
    // ---- Q convert in-kernel (1 item/thread) ----
    {
        int r = tid >> 4, dq = tid & 15;
        float4 v = ((const float4*)Q)[((size_t)(bh * S_LEN) + q0 + r) * 16 + dq];
        float x0 = v.x * 0.125f, x1 = v.y * 0.125f, x2 = v.z * 0.125f, x3 = v.w * 0.125f;
        int ks = dq >> 2;
        int p0 = PERM((2 * dq) & 7), p1 = PERM((2 * dq + 1) & 7);
        uint32_t* qr2 = su + O_Q + r * SK;
        uint32_t g0 = pk(x0, x1), g1 = pk(x2, x3);
        int o0 = ks * 16 + ((p0 >> 1) << 2) + (p0 & 1);
        int o1 = ks * 16 + ((p1 >> 1) << 2) + (p1 & 1);
        qr2[o0] = g0; qr2[o0 + 2] = pkres(x0, x1, g0);
        qr2[o1] = g1; qr2[o1 + 2] = pkres(x2, x3, g1);
    }
    // ---- zero-fill attn outside the 320-wide strip ----
    {
        float* t0 = attn + (size_t)q0 * S_LEN;
        if (4 * tid + 3 < klo || 4 * tid >= klo + KW) {
            const float4 z4 = make_float4(0.f, 0.f, 0.f, 0.f);
            #pragma unroll 8
            for (int r = 0; r < TQ; ++r)
                ((float4*)(t0 + (size_t)r * S_LEN))[tid] = z4;
        }
    }
    __syncthreads();

    // ---- warp geometry ----
    const int qr = m * 16, nb = nw * 40;
    const int glo = max(0, q0 + qr - 127) - klo;
    const int ghi = min(S_LEN - 1, q0 + qr + 15 + 127) - klo;
    bool alive[5];
    #pragma unroll
    for (int f = 0; f < 5; ++f)
        alive[f] = (nb + 8 * f + 7 >= glo) && (nb + 8 * f <= ghi);

    // ---- GEMM1: C[32x320] = Qs . K^T (bf16 3-term, LDS.128 frags) ----
    float4 C[5];
    #pragma unroll
    for (int f = 0; f < 5; ++f) C[f] = make_float4(0.f, 0.f, 0.f, 0.f);

    #pragma unroll
    for (int ks = 0; ks < 4; ++ks) {
        uint4 qv0 = *(const uint4*)(su + O_Q + (qr + gid) * SK + ks * 16 + tig * 4);
        uint4 qv1 = *(const uint4*)(su + O_Q + (qr + gid + 8) * SK + ks * 16 + tig * 4);
        #pragma unroll
        for (int f = 0; f < 5; ++f) {
            if (!alive[f]) continue;
            uint4 kv = *(const uint4*)(su + O_K + (nb + 8 * f + gid) * SK + ks * 16 + tig * 4);
            mmabf(C[f], qv0.x, qv1.x, qv0.y, qv1.y, kv.x, kv.y);   // hh
            mmabf(C[f], qv0.z, qv1.z, qv0.w, qv1.w, kv.x, kv.y);   // lh
            mmabf(C[f], qv0.x, qv1.x, qv0.y, qv1.y, kv.z, kv.w);   // hl
        }
    }

    // ---- band mask + local row stats ----
    const int r0g = q0 + qr + gid;
    float mr0 = -INFINITY, mr1 = -INFINITY;
    #pragma unroll
    for (int f = 0; f < 5; ++f) {
        int k0 = klo + nb + 8 * f + 2 * tig;
        bool v0 = (unsigned)(r0g     - k0     + WIN - 1) <= 2 * (WIN - 1) && k0     <= khi;
        bool v1 = (unsigned)(r0g     - k0 - 1 + WIN - 1) <= 2 * (WIN - 1) && k0 + 1 <= khi;
        bool v2 = (unsigned)(r0g + 8 - k0     + WIN - 1) <= 2 * (WIN - 1) && k0     <= khi;
        bool v3 = (unsigned)(r0g + 8 - k0 - 1 + WIN - 1) <= 2 * (WIN - 1) && k0 + 1 <= khi;
        C[f].x = v0 ? C[f].x : -INFINITY;
        C[f].y = v1 ? C[f].y : -INFINITY;
        C[f].z = v2 ? C[f].z : -INFINITY;
        C[f].w = v3 ? C[f].w : -INFINITY;
        mr0 = fmaxf(mr0, fmaxf(C[f].x, C[f].y));
        mr1 = fmaxf(mr1, fmaxf(C[f].z, C[f].w));
    }
    #pragma unroll
    for (int off = 1; off <= 2; off <<= 1) {
        mr0 = fmaxf(mr0, __shfl_xor_sync(0xffffffffu, mr0, off));
        mr1 = fmaxf(mr1, __shfl_xor_sync(0xffffffffu, mr1, off));
    }
    mr0 = fmaxf(mr0, -1e30f); mr1 = fmaxf(mr1, -1e30f);
    float sr0 = 0.f, sr1 = 0.f;
    #pragma unroll
    for (int f = 0; f < 5; ++f) {
        sr0 += __expf(C[f].x - mr0) + __expf(C[f].y - mr0);
        sr1 += __expf(C[f].z - mr1) + __expf(C[f].w - mr1);
    }
    #pragma unroll
    for (int off = 1; off <= 2; off <<= 1) {
        sr0 += __shfl_xor_sync(0xffffffffu, sr0, off);
        sr1 += __shfl_xor_sync(0xffffffffu, sr1, off);
    }
    if (tig == 0) {
        sf[O_MS + nw * 32 + qr + gid]     = mr0;  sf[O_SS + nw * 32 + qr + gid]     = sr0;
        sf[O_MS + nw * 32 + qr + gid + 8] = mr1;  sf[O_SS + nw * 32 + qr + gid + 8] = sr1;
    }
    __syncthreads();   // K dead; stats visible

    // ---- Vt copy into K region ----
    {
        int d = tid >> 3, c0 = tid & 7;
        const uint4* src = (const uint4*)(d_Vt + (size_t)(bh * DH + d) * VROW + klo2 * 2);
        uint4* dst = (uint4*)(su + d * SV);
        #pragma unroll
        for (int j = 0; j < 10; ++j) dst[c0 + j * 8] = src[c0 + j * 8];
    }

    // ---- global softmax constant per row ----
    float M0 = -INFINITY, M1 = -INFINITY;
    #pragma unroll
    for (int n2 = 0; n2 < 8; ++n2) {
        M0 = fmaxf(M0, sf[O_MS + n2 * 32 + qr + gid]);
        M1 = fmaxf(M1, sf[O_MS + n2 * 32 + qr + gid + 8]);
    }
    float S0 = 0.f, S1 = 0.f;
    #pragma unroll
    for (int n2 = 0; n2 < 8; ++n2) {
        S0 += sf[O_SS + n2 * 32 + qr + gid]     * __expf(sf[O_MS + n2 * 32 + qr + gid]     - M0);
        S1 += sf[O_SS + n2 * 32 + qr + gid + 8] * __expf(sf[O_MS + n2 * 32 + qr + gid + 8] - M1);
    }
    const float Cr0 = M0 + __logf(S0);
    const float Cr1 = M1 + __logf(S1);
    __syncthreads();   // Vt ready

    // ---- p = exp(C - Cr) (registers only; stores deferred) ----
    #pragma unroll
    for (int f = 0; f < 5; ++f) {
        C[f] = make_float4(__expf(C[f].x - Cr0), __expf(C[f].y - Cr0),
                           __expf(C[f].z - Cr1), __expf(C[f].w - Cr1));
    }

    // ---- GEMM2: ctx = P . V ----
    float4 acc[8];
    #pragma unroll
    for (int nt = 0; nt < 8; ++nt) acc[nt] = make_float4(0.f, 0.f, 0.f, 0.f);
    const int chunk0 = (nb - 8 * (nw & 1)) >> 4;
    if (!(nw & 1)) { G2STEP(0, 1, 0); G2STEP(2, 3, 1); G2STEP(4, 5, 2); }
    else           { G2STEP(-1, 0, 0); G2STEP(1, 2, 1); G2STEP(3, 4, 2); }
    __syncthreads();   // Vt dead

    // ---- stage p into freed region + combine-slot writes ----
    #pragma unroll
    for (int f = 0; f < 5; ++f) {
        int col = nb + 8 * f + 2 * tig;
        *(float2*)(sf + O_STG + (qr + gid)     * ST + col) = make_float2(C[f].x, C[f].y);
        *(float2*)(sf + O_STG + (qr + gid + 8) * ST + col) = make_float2(C[f].z, C[f].w);
    }
    if (nw) {
        float4* sp = (float4*)sf + (m * 7 + nw - 1) * 256;
        #pragma unroll
        for (int nt = 0; nt < 8; ++nt) sp[nt * 32 + lane] = acc[nt];
    }
    __syncthreads();

    // ---- coalesced strip store (all threads) + ctx combine (nw==0 warps) ----
    {
        const int klo4 = klo >> 2;
        #pragma unroll
        for (int j = 0; j < 5; ++j) {
            int i = tid + j * NT;              // 0..2559 over 32 rows x 80 float4
            int r = i / 80, c4 = i - r * 80;
            int g4 = klo4 + c4;
            if (g4 < S_LEN / 4) {
                const float* sp2 = sf + O_STG + r * ST + c4 * 4;
                ((float4*)(attn + (size_t)(q0 + r) * S_LEN))[g4] =
                    make_float4(sp2[0], sp2[1], sp2[2], sp2[3]);
            }
        }
    }
    if (!nw) {
        #pragma unroll
        for (int s = 0; s < 7; ++s) {
            const float4* sp = (const float4*)sf + (m * 7 + s) * 256;
            #pragma unroll
            for (int nt = 0; nt < 8; ++nt) {
                float4 t = sp[nt * 32 + lane];
                acc[nt].x += t.x; acc[nt].y += t.y; acc[nt].z += t.z; acc[nt].w += t.w;
            }
        }
        float* cb = ctx_out + ((size_t)bh * S_LEN + q0 + qr) * DH;
        #pragma unroll
        for (int nt = 0; nt < 8; ++nt) {
            int d0 = nt * 8 + 2 * tig;
            *(float2*)(cb + gid * DH + d0)       = make_float2(acc[nt].x, acc[nt].y);
            *(float2*)(cb + (gid + 8) * DH + d0) = make_float2(acc[nt].z, acc[nt].w);
        }
    }
}

extern "C" void kernel_launch(void* const* d_in, const int* in_sizes, int n_in,
                              void* d_out, int out_size)
{
    const float* Q = (const float*)d_in[0];
    const float* K = (const float*)d_in[1];
    const float* V = (const float*)d_in[2];

    float* out  = (float*)d_out;
    float* ctx  = out;                                 // [B,H,S,D] first
    float* attn = out + (size_t)NB * NH * S_LEN * DH;  // then [B,H,S,S]

    prep_kernel<<<(NB * NH * S_LEN * 16) / 256, 256>>>(K, V);

    cudaFuncSetAttribute(band_attn_bf16,
                         cudaFuncAttributeMaxDynamicSharedMemorySize, SMEM_B);
    dim3 grid(S_LEN / TQ, NH, NB);
    band_attn_bf16<<<grid, NT, SMEM_B>>>(Q, K, V, ctx, attn);
}

// round 15
// speedup vs baseline: 1.1580x; 1.1580x over previous
#include <cuda_runtime.h>
#include <cuda_bf16.h>
#include <math.h>
#include <stdint.h>

#define S_LEN 2048
#define DH    64
#define NB    2
#define NH    8
#define WIN   128
#define TQ    32
#define NT    512
#define KW    320
#define SK    80     // K/Q smem row stride (u32); LDS.128 conflict-free
#define SV    336    // Vt smem row stride (u32)
#define VROW  2208   // Vt gmem row stride (u32)

// u32 smem offsets
#define O_K    0       // K tile 320*80 = 25600 (Vt overlay 21504; slots after)
#define O_Q    25600   // Q tile 32*80 = 2560
#define O_MS   28160   // f32 [8][32]
#define O_SS   28416
#define SM_U32 28672
#define SMEM_B (SM_U32 * 4)   // 114688 B -> 2 CTAs/SM

#define PERM(p) ((((p) & 3) << 1) | ((p) >> 2))
#define FI(f)   ((f) < 0 ? 0 : ((f) > 4 ? 4 : (f)))

// pre-converted tiles (static zero-init; ~17 MB)
__device__ uint32_t d_Kp[NB * NH * S_LEN * 64];
__device__ uint32_t d_Vt[NB * NH * DH * VROW];

__device__ __forceinline__ uint32_t pk(float x, float y) {
    __nv_bfloat162 h = __floats2bfloat162_rn(x, y);
    return *(uint32_t*)&h;
}
__device__ __forceinline__ uint32_t pkres(float x, float y, uint32_t h) {
    __nv_bfloat162 hh = *(__nv_bfloat162*)&h;
    return pk(x - __bfloat162float(hh.x), y - __bfloat162float(hh.y));
}
__device__ __forceinline__ void mmabf(float4& c, uint32_t a0, uint32_t a1, uint32_t a2,
                                      uint32_t a3, uint32_t b0, uint32_t b1) {
    asm("mma.sync.aligned.m16n8k16.row.col.f32.bf16.bf16.f32 "
        "{%0,%1,%2,%3}, {%4,%5,%6,%7}, {%8,%9}, {%0,%1,%2,%3};"
        : "+f"(c.x), "+f"(c.y), "+f"(c.z), "+f"(c.w)
        : "r"(a0), "r"(a1), "r"(a2), "r"(a3), "r"(b0), "r"(b1));
}
__device__ __forceinline__ uint32_t smem_u32(const void* p) {
    uint32_t a;
    asm("{ .reg .u64 t; cvta.to.shared.u64 t, %1; cvt.u32.u64 %0, t; }" : "=r"(a) : "l"(p));
    return a;
}
__device__ __forceinline__ void cpa16(uint32_t dst, const void* src) {
    asm volatile("cp.async.cg.shared.global [%0], [%1], 16;" :: "r"(dst), "l"(src) : "memory");
}
#define CPA_COMMIT() asm volatile("cp.async.commit_group;" ::: "memory")
#define CPA_WAIT0()  asm volatile("cp.async.wait_group 0;" ::: "memory")

// ---- prep: convert K and V once, hi/lo interleaved final layouts ----
__global__ void __launch_bounds__(256)
prep_kernel(const float* __restrict__ K, const float* __restrict__ V)
{
    int idx = blockIdx.x * blockDim.x + threadIdx.x;     // 524288
    {   // K rows
        int dq = idx & 15, r = (idx >> 4) & (S_LEN - 1), bh = idx >> 15;
        int ks = dq >> 2;
        int p0 = PERM((2 * dq) & 7), p1 = PERM((2 * dq + 1) & 7);
        size_t rowi = (size_t)(bh * S_LEN + r);
        float4 kv = ((const float4*)K)[rowi * 16 + dq];
        uint32_t* kr = d_Kp + rowi * 64;
        uint32_t h0 = pk(kv.x, kv.y), h1 = pk(kv.z, kv.w);
        int o0 = ks * 16 + ((p0 >> 1) << 2) + (p0 & 1);
        int o1 = ks * 16 + ((p1 >> 1) << 2) + (p1 & 1);
        kr[o0] = h0; kr[o0 + 2] = pkres(kv.x, kv.y, h0);
        kr[o1] = h1; kr[o1 + 2] = pkres(kv.z, kv.w, h1);
    }
    if (idx < NB * NH * 16 * 1024) {   // V transpose
        int kp = idx & 1023, dq = (idx >> 10) & 15, bh = idx >> 14;
        float4 v0 = ((const float4*)V)[((size_t)(bh * S_LEN) + 2 * kp) * 16 + dq];
        float4 v1 = ((const float4*)V)[((size_t)(bh * S_LEN) + 2 * kp + 1) * 16 + dq];
        int ch = kp >> 3, uu = PERM(kp & 7);
        #pragma unroll
        for (int j = 0; j < 4; ++j) {
            float x0 = (j == 0) ? v0.x : (j == 1) ? v0.y : (j == 2) ? v0.z : v0.w;
            float x1 = (j == 0) ? v1.x : (j == 1) ? v1.y : (j == 2) ? v1.z : v1.w;
            int d = 4 * dq + j;
            int e = uu ^ (((d >> 2) & 3) << 1);
            uint32_t o = (uint32_t)(bh * DH + d) * VROW + ch * 16 + ((e >> 1) << 2) + (e & 1);
            uint32_t h = pk(x0, x1);
            d_Vt[o] = h;
            d_Vt[o + 2] = pkres(x0, x1, h);
        }
    }
}

// GEMM2 k16 step (A = P frags; FA/FB outside [0,4] -> zeros)
#define G2STEP(FA, FB, C2) do {                                                   \
    int ck = chunk0 + (C2);                                                       \
    if (ck * 16 + 15 >= glo && ck * 16 <= ghi) {                                  \
        uint32_t ah0, ah1, ah2, ah3, al0, al1, al2, al3;                          \
        if ((FA) >= 0) {                                                          \
            float4 pa = C[FI(FA)];                                                \
            ah0 = pk(pa.x, pa.y); al0 = pkres(pa.x, pa.y, ah0);                   \
            ah1 = pk(pa.z, pa.w); al1 = pkres(pa.z, pa.w, ah1);                   \
        } else { ah0 = ah1 = al0 = al1 = 0u; }                                    \
        if ((FB) <= 4) {                                                          \
            float4 pb = C[FI(FB)];                                                \
            ah2 = pk(pb.x, pb.y); al2 = pkres(pb.x, pb.y, ah2);                   \
            ah3 = pk(pb.z, pb.w); al3 = pkres(pb.z, pb.w, ah3);                   \
        } else { ah2 = ah3 = al2 = al3 = 0u; }                                    \
        _Pragma("unroll")                                                         \
        for (int nt = 0; nt < 8; ++nt) {                                          \
            uint32_t dr = nt * 8 + gid;                                           \
            uint32_t bi = dr * SV + ck * 16 + ((tig ^ ((dr >> 2) & 3u)) << 2);    \
            uint4 bv = *(const uint4*)(su + bi);                                  \
            mmabf(acc[nt], ah0, ah1, ah2, ah3, bv.x, bv.y);                       \
            mmabf(acc[nt], al0, al1, al2, al3, bv.x, bv.y);                       \
            mmabf(acc[nt], ah0, ah1, ah2, ah3, bv.z, bv.w);                       \
        }                                                                         \
    }                                                                             \
} while (0)

__global__ void __launch_bounds__(NT, 2)
band_attn_bf16(const float* __restrict__ Q, const float* __restrict__ K,
               const float* __restrict__ V, float* __restrict__ ctx_out,
               float* __restrict__ attn_out)
{
    extern __shared__ float smem[];
    uint32_t* su = (uint32_t*)smem;
    float*    sf = smem;
    const uint32_t sbase = smem_u32(smem);

    const int tid = threadIdx.x, w = tid >> 5, lane = tid & 31;
    const int gid = lane >> 2, tig = lane & 3;
    const int m = w >> 3, nw = w & 7;
    const int bh = blockIdx.z * NH + blockIdx.y;
    const int q0 = blockIdx.x * TQ;
    const int klo = max(0, q0 - 128);
    const int klo2 = klo >> 1;
    const int khi = min(S_LEN - 1, q0 + TQ - 1 + WIN - 1);
    const int cnt = khi - klo + 1;             // <= 287

    float* attn = attn_out + (size_t)bh * S_LEN * S_LEN;

    // ---- K tile copy via cp.async ----
    for (int i = tid; i < cnt * 16; i += NT) {
        int r = i >> 4, c = i & 15;
        cpa16(sbase + (O_K + r * SK + c * 4) * 4,
              d_Kp + ((size_t)(bh * S_LEN) + klo + r) * 64 + c * 4);
    }
    CPA_COMMIT();
    // ---- Q convert in-kernel (1 item/thread) ----
    {
        int r = tid >> 4, dq = tid & 15;
        float4 v = ((const float4*)Q)[((size_t)(bh * S_LEN) + q0 + r) * 16 + dq];
        float x0 = v.x * 0.125f, x1 = v.y * 0.125f, x2 = v.z * 0.125f, x3 = v.w * 0.125f;
        int ks = dq >> 2;
        int p0 = PERM((2 * dq) & 7), p1 = PERM((2 * dq + 1) & 7);
        uint32_t* qr2 = su + O_Q + r * SK;
        uint32_t g0 = pk(x0, x1), g1 = pk(x2, x3);
        int o0 = ks * 16 + ((p0 >> 1) << 2) + (p0 & 1);
        int o1 = ks * 16 + ((p1 >> 1) << 2) + (p1 & 1);
        qr2[o0] = g0; qr2[o0 + 2] = pkres(x0, x1, g0);
        qr2[o1] = g1; qr2[o1 + 2] = pkres(x2, x3, g1);
    }
    // ---- zero-fill attn outside the 320-wide strip ----
    {
        float* t0 = attn + (size_t)q0 * S_LEN;
        if (4 * tid + 3 < klo || 4 * tid >= klo + KW) {
            const float4 z4 = make_float4(0.f, 0.f, 0.f, 0.f);
            #pragma unroll 8
            for (int r = 0; r < TQ; ++r)
                ((float4*)(t0 + (size_t)r * S_LEN))[tid] = z4;
        }
    }
    CPA_WAIT0();
    __syncthreads();

    // ---- warp geometry + frag classes (all warp-uniform) ----
    const int qr = m * 16, nb = nw * 40;
    const int rbase = q0 + qr;
    const int glo = max(0, rbase - 127) - klo;
    const int ghi = min(S_LEN - 1, rbase + 15 + 127) - klo;
    bool alive[5], fullin[5];
    #pragma unroll
    for (int f = 0; f < 5; ++f) {
        int flo = klo + nb + 8 * f, fhi = flo + 7;
        alive[f]  = (fhi - klo >= glo) && (flo - klo <= ghi);
        fullin[f] = (flo >= rbase - 112) && (fhi <= rbase + 127) && (fhi <= khi);
    }

    // ---- GEMM1: C[32x320] = Qs . K^T (bf16 3-term, LDS.128 frags) ----
    float4 C[5];
    #pragma unroll
    for (int f = 0; f < 5; ++f) C[f] = make_float4(0.f, 0.f, 0.f, 0.f);

    #pragma unroll
    for (int ks = 0; ks < 4; ++ks) {
        uint4 qv0 = *(const uint4*)(su + O_Q + (qr + gid) * SK + ks * 16 + tig * 4);
        uint4 qv1 = *(const uint4*)(su + O_Q + (qr + gid + 8) * SK + ks * 16 + tig * 4);
        #pragma unroll
        for (int f = 0; f < 5; ++f) {
            if (!alive[f]) continue;
            uint4 kv = *(const uint4*)(su + O_K + (nb + 8 * f + gid) * SK + ks * 16 + tig * 4);
            mmabf(C[f], qv0.x, qv1.x, qv0.y, qv1.y, kv.x, kv.y);   // hh
            mmabf(C[f], qv0.z, qv1.z, qv0.w, qv1.w, kv.x, kv.y);   // lh
            mmabf(C[f], qv0.x, qv1.x, qv0.y, qv1.y, kv.z, kv.w);   // hl
        }
    }

    // ---- mask: full-in frags skip all per-element ALU ----
    const int r0g = rbase + gid;
    #pragma unroll
    for (int f = 0; f < 5; ++f) {
        if (fullin[f]) continue;
        if (!alive[f]) { C[f] = make_float4(-INFINITY, -INFINITY, -INFINITY, -INFINITY); continue; }
        int k0 = klo + nb + 8 * f + 2 * tig;
        bool v0 = (unsigned)(r0g     - k0     + WIN - 1) <= 2 * (WIN - 1) && k0     <= khi;
        bool v1 = (unsigned)(r0g     - k0 - 1 + WIN - 1) <= 2 * (WIN - 1) && k0 + 1 <= khi;
        bool v2 = (unsigned)(r0g + 8 - k0     + WIN - 1) <= 2 * (WIN - 1) && k0     <= khi;
        bool v3 = (unsigned)(r0g + 8 - k0 - 1 + WIN - 1) <= 2 * (WIN - 1) && k0 + 1 <= khi;
        C[f].x = v0 ? C[f].x : -INFINITY;
        C[f].y = v1 ? C[f].y : -INFINITY;
        C[f].z = v2 ? C[f].z : -INFINITY;
        C[f].w = v3 ? C[f].w : -INFINITY;
    }

    // ---- local row stats ----
    float mr0 = -INFINITY, mr1 = -INFINITY;
    #pragma unroll
    for (int f = 0; f < 5; ++f) {
        mr0 = fmaxf(mr0, fmaxf(C[f].x, C[f].y));
        mr1 = fmaxf(mr1, fmaxf(C[f].z, C[f].w));
    }
    #pragma unroll
    for (int off = 1; off <= 2; off <<= 1) {
        mr0 = fmaxf(mr0, __shfl_xor_sync(0xffffffffu, mr0, off));
        mr1 = fmaxf(mr1, __shfl_xor_sync(0xffffffffu, mr1, off));
    }
    mr0 = fmaxf(mr0, -1e30f); mr1 = fmaxf(mr1, -1e30f);
    float sr0 = 0.f, sr1 = 0.f;
    #pragma unroll
    for (int f = 0; f < 5; ++f) {
        sr0 += __expf(C[f].x - mr0) + __expf(C[f].y - mr0);
        sr1 += __expf(C[f].z - mr1) + __expf(C[f].w - mr1);
    }
    #pragma unroll
    for (int off = 1; off <= 2; off <<= 1) {
        sr0 += __shfl_xor_sync(0xffffffffu, sr0, off);
        sr1 += __shfl_xor_sync(0xffffffffu, sr1, off);
    }
    if (tig == 0) {
        sf[O_MS + nw * 32 + qr + gid]     = mr0;  sf[O_SS + nw * 32 + qr + gid]     = sr0;
        sf[O_MS + nw * 32 + qr + gid + 8] = mr1;  sf[O_SS + nw * 32 + qr + gid + 8] = sr1;
    }
    __syncthreads();   // K dead; stats visible

    // ---- Vt copy into K region via cp.async (overlaps softmax-const math) ----
    {
        int d = tid >> 3, c0 = tid & 7;
        size_t gb = (size_t)(bh * DH + d) * VROW + klo2 * 2;
        #pragma unroll
        for (int j = 0; j < 10; ++j)
            cpa16(sbase + (d * SV + (c0 + j * 8) * 4) * 4, d_Vt + gb + (c0 + j * 8) * 4);
        CPA_COMMIT();
    }

    // ---- global softmax constant per row ----
    float M0 = -INFINITY, M1 = -INFINITY;
    #pragma unroll
    for (int n2 = 0; n2 < 8; ++n2) {
        M0 = fmaxf(M0, sf[O_MS + n2 * 32 + qr + gid]);
        M1 = fmaxf(M1, sf[O_MS + n2 * 32 + qr + gid + 8]);
    }
    float S0 = 0.f, S1 = 0.f;
    #pragma unroll
    for (int n2 = 0; n2 < 8; ++n2) {
        S0 += sf[O_SS + n2 * 32 + qr + gid]     * __expf(sf[O_MS + n2 * 32 + qr + gid]     - M0);
        S1 += sf[O_SS + n2 * 32 + qr + gid + 8] * __expf(sf[O_MS + n2 * 32 + qr + gid + 8] - M1);
    }
    const float Cr0 = M0 + __logf(S0);
    const float Cr1 = M1 + __logf(S1);
    CPA_WAIT0();
    __syncthreads();   // Vt ready

    // ---- p = exp(C - Cr); attn band stores (unguarded for full-in frags) ----
    #pragma unroll
    for (int f = 0; f < 5; ++f) {
        float p0 = __expf(C[f].x - Cr0), p1 = __expf(C[f].y - Cr0);
        float p2 = __expf(C[f].z - Cr1), p3 = __expf(C[f].w - Cr1);
        C[f] = make_float4(p0, p1, p2, p3);
        int k0 = klo + nb + 8 * f + 2 * tig;
        if (fullin[f]) {
            *(float2*)(attn + (size_t)r0g       * S_LEN + k0) = make_float2(p0, p1);
            *(float2*)(attn + (size_t)(r0g + 8) * S_LEN + k0) = make_float2(p2, p3);
        } else if (k0 < S_LEN) {
            *(float2*)(attn + (size_t)r0g       * S_LEN + k0) = make_float2(p0, p1);
            *(float2*)(attn + (size_t)(r0g + 8) * S_LEN + k0) = make_float2(p2, p3);
        }
    }

    // ---- GEMM2: ctx = P . V ----
    float4 acc[8];
    #pragma unroll
    for (int nt = 0; nt < 8; ++nt) acc[nt] = make_float4(0.f, 0.f, 0.f, 0.f);
    const int chunk0 = (nb - 8 * (nw & 1)) >> 4;
    if (!(nw & 1)) { G2STEP(0, 1, 0); G2STEP(2, 3, 1); G2STEP(4, 5, 2); }
    else           { G2STEP(-1, 0, 0); G2STEP(1, 2, 1); G2STEP(3, 4, 2); }
    __syncthreads();   // Vt dead

    // ---- combine 8 nw partials ----
    if (nw) {
        float4* sp = (float4*)sf + (m * 7 + nw - 1) * 256;
        #pragma unroll
        for (int nt = 0; nt < 8; ++nt) sp[nt * 32 + lane] = acc[nt];
    }
    __syncthreads();
    if (!nw) {
        #pragma unroll
        for (int s = 0; s < 7; ++s) {
            const float4* sp = (const float4*)sf + (m * 7 + s) * 256;
            #pragma unroll
            for (int nt = 0; nt < 8; ++nt) {
                float4 t = sp[nt * 32 + lane];
                acc[nt].x += t.x; acc[nt].y += t.y; acc[nt].z += t.z; acc[nt].w += t.w;
            }
        }
        float* cb = ctx_out + ((size_t)bh * S_LEN + q0 + qr) * DH;
        #pragma unroll
        for (int nt = 0; nt < 8; ++nt) {
            int d0 = nt * 8 + 2 * tig;
            *(float2*)(cb + gid * DH + d0)       = make_float2(acc[nt].x, acc[nt].y);
            *(float2*)(cb + (gid + 8) * DH + d0) = make_float2(acc[nt].z, acc[nt].w);
        }
    }
}

extern "C" void kernel_launch(void* const* d_in, const int* in_sizes, int n_in,
                              void* d_out, int out_size)
{
    const float* Q = (const float*)d_in[0];
    const float* K = (const float*)d_in[1];
    const float* V = (const float*)d_in[2];

    float* out  = (float*)d_out;
    float* ctx  = out;                                 // [B,H,S,D] first
    float* attn = out + (size_t)NB * NH * S_LEN * DH;  // then [B,H,S,S]

    prep_kernel<<<(NB * NH * S_LEN * 16) / 256, 256>>>(K, V);

    cudaFuncSetAttribute(band_attn_bf16,
                         cudaFuncAttributeMaxDynamicSharedMemorySize, SMEM_B);
    dim3 grid(S_LEN / TQ, NH, NB);
    band_attn_bf16<<<grid, NT, SMEM_B>>>(Q, K, V, ctx, attn);
}

// round 16
// speedup vs baseline: 1.1831x; 1.0217x over previous
#include <cuda_runtime.h>
#include <cuda_bf16.h>
#include <math.h>
#include <stdint.h>

#define S_LEN 2048
#define DH    64
#define NB    2
#define NH    8
#define WIN   128
#define TQ    32
#define NT    512
#define KW    320
#define SK    80     // K/Q smem row stride (u32); LDS.128 conflict-free
#define SV    336    // Vt smem row stride (u32)
#define VROW  2208   // Vt gmem row stride (u32)

// u32 smem offsets
#define O_K    0       // K tile 320*80 = 25600 (Vt overlay 21504; slots after)
#define O_Q    25600   // Q tile 32*80 = 2560
#define O_MS   28160   // f32 [8][32]
#define O_SS   28416
#define SM_U32 28672
#define SMEM_B (SM_U32 * 4)   // 114688 B -> 2 CTAs/SM

#define PERM(p) ((((p) & 3) << 1) | ((p) >> 2))
#define FI(f)   ((f) < 0 ? 0 : ((f) > 4 ? 4 : (f)))

// pre-converted tiles (static zero-init; ~17 MB)
__device__ uint32_t d_Kp[NB * NH * S_LEN * 64];
__device__ uint32_t d_Vt[NB * NH * DH * VROW];

__device__ __forceinline__ uint32_t pk(float x, float y) {
    __nv_bfloat162 h = __floats2bfloat162_rn(x, y);
    return *(uint32_t*)&h;
}
__device__ __forceinline__ uint32_t pkres(float x, float y, uint32_t h) {
    __nv_bfloat162 hh = *(__nv_bfloat162*)&h;
    return pk(x - __bfloat162float(hh.x), y - __bfloat162float(hh.y));
}
__device__ __forceinline__ void mmabf(float4& c, uint32_t a0, uint32_t a1, uint32_t a2,
                                      uint32_t a3, uint32_t b0, uint32_t b1) {
    asm("mma.sync.aligned.m16n8k16.row.col.f32.bf16.bf16.f32 "
        "{%0,%1,%2,%3}, {%4,%5,%6,%7}, {%8,%9}, {%0,%1,%2,%3};"
        : "+f"(c.x), "+f"(c.y), "+f"(c.z), "+f"(c.w)
        : "r"(a0), "r"(a1), "r"(a2), "r"(a3), "r"(b0), "r"(b1));
}
__device__ __forceinline__ uint32_t smem_u32(const void* p) {
    uint32_t a;
    asm("{ .reg .u64 t; cvta.to.shared.u64 t, %1; cvt.u32.u64 %0, t; }" : "=r"(a) : "l"(p));
    return a;
}
__device__ __forceinline__ void cpa16(uint32_t dst, const void* src) {
    asm volatile("cp.async.cg.shared.global [%0], [%1], 16;" :: "r"(dst), "l"(src) : "memory");
}
#define CPA_COMMIT() asm volatile("cp.async.commit_group;" ::: "memory")
#define CPA_WAIT0()  asm volatile("cp.async.wait_group 0;" ::: "memory")

// ---- prep: convert K and V once, hi/lo interleaved final layouts ----
__global__ void __launch_bounds__(256)
prep_kernel(const float* __restrict__ K, const float* __restrict__ V)
{
    int idx = blockIdx.x * blockDim.x + threadIdx.x;     // 524288
    {   // K rows
        int dq = idx & 15, r = (idx >> 4) & (S_LEN - 1), bh = idx >> 15;
        int ks = dq >> 2;
        int p0 = PERM((2 * dq) & 7), p1 = PERM((2 * dq + 1) & 7);
        size_t rowi = (size_t)(bh * S_LEN + r);
        float4 kv = ((const float4*)K)[rowi * 16 + dq];
        uint32_t* kr = d_Kp + rowi * 64;
        uint32_t h0 = pk(kv.x, kv.y), h1 = pk(kv.z, kv.w);
        int o0 = ks * 16 + ((p0 >> 1) << 2) + (p0 & 1);
        int o1 = ks * 16 + ((p1 >> 1) << 2) + (p1 & 1);
        kr[o0] = h0; kr[o0 + 2] = pkres(kv.x, kv.y, h0);
        kr[o1] = h1; kr[o1 + 2] = pkres(kv.z, kv.w, h1);
    }
    if (idx < NB * NH * 16 * 1024) {   // V transpose
        int kp = idx & 1023, dq = (idx >> 10) & 15, bh = idx >> 14;
        float4 v0 = ((const float4*)V)[((size_t)(bh * S_LEN) + 2 * kp) * 16 + dq];
        float4 v1 = ((const float4*)V)[((size_t)(bh * S_LEN) + 2 * kp + 1) * 16 + dq];
        int ch = kp >> 3, uu = PERM(kp & 7);
        #pragma unroll
        for (int j = 0; j < 4; ++j) {
            float x0 = (j == 0) ? v0.x : (j == 1) ? v0.y : (j == 2) ? v0.z : v0.w;
            float x1 = (j == 0) ? v1.x : (j == 1) ? v1.y : (j == 2) ? v1.z : v1.w;
            int d = 4 * dq + j;
            int e = uu ^ (((d >> 2) & 3) << 1);
            uint32_t o = (uint32_t)(bh * DH + d) * VROW + ch * 16 + ((e >> 1) << 2) + (e & 1);
            uint32_t h = pk(x0, x1);
            d_Vt[o] = h;
            d_Vt[o + 2] = pkres(x0, x1, h);
        }
    }
}

// GEMM2 k16 step (A = P frags; FA/FB outside [0,4] -> zeros)
#define G2STEP(FA, FB, C2) do {                                                   \
    int ck = chunk0 + (C2);                                                       \
    if (ck * 16 + 15 >= glo && ck * 16 <= ghi) {                                  \
        uint32_t ah0, ah1, ah2, ah3, al0, al1, al2, al3;                          \
        if ((FA) >= 0) {                                                          \
            float4 pa = C[FI(FA)];                                                \
            ah0 = pk(pa.x, pa.y); al0 = pkres(pa.x, pa.y, ah0);                   \
            ah1 = pk(pa.z, pa.w); al1 = pkres(pa.z, pa.w, ah1);                   \
        } else { ah0 = ah1 = al0 = al1 = 0u; }                                    \
        if ((FB) <= 4) {                                                          \
            float4 pb = C[FI(FB)];                                                \
            ah2 = pk(pb.x, pb.y); al2 = pkres(pb.x, pb.y, ah2);                   \
            ah3 = pk(pb.z, pb.w); al3 = pkres(pb.z, pb.w, ah3);                   \
        } else { ah2 = ah3 = al2 = al3 = 0u; }                                    \
        _Pragma("unroll")                                                         \
        for (int nt = 0; nt < 8; ++nt) {                                          \
            uint32_t dr = nt * 8 + gid;                                           \
            uint32_t bi = dr * SV + ck * 16 + ((tig ^ ((dr >> 2) & 3u)) << 2);    \
            uint4 bv = *(const uint4*)(su + bi);                                  \
            mmabf(acc[nt], ah0, ah1, ah2, ah3, bv.x, bv.y);                       \
            mmabf(acc[nt], al0, al1, al2, al3, bv.x, bv.y);                       \
            mmabf(acc[nt], ah0, ah1, ah2, ah3, bv.z, bv.w);                       \
        }                                                                         \
    }                                                                             \
} while (0)

__global__ void __launch_bounds__(NT, 2)
band_attn_bf16(const float* __restrict__ Q, const float* __restrict__ K,
               const float* __restrict__ V, float* __restrict__ ctx_out,
               float* __restrict__ attn_out)
{
    extern __shared__ float smem[];
    uint32_t* su = (uint32_t*)smem;
    float*    sf = smem;
    const uint32_t sbase = smem_u32(smem);

    const int tid = threadIdx.x, w = tid >> 5, lane = tid & 31;
    const int gid = lane >> 2, tig = lane & 3;
    const int m = w >> 3, nw = w & 7;
    const int bh = blockIdx.z * NH + blockIdx.y;
    const int q0 = blockIdx.x * TQ;
    const int klo = max(0, q0 - 128);
    const int klo2 = klo >> 1;
    const int khi = min(S_LEN - 1, q0 + TQ - 1 + WIN - 1);
    const int cnt = khi - klo + 1;             // <= 287

    float* attn = attn_out + (size_t)bh * S_LEN * S_LEN;

    // ---- K tile copy via cp.async ----
    for (int i = tid; i < cnt * 16; i += NT) {
        int r = i >> 4, c = i & 15;
        cpa16(sbase + (O_K + r * SK + c * 4) * 4,
              d_Kp + ((size_t)(bh * S_LEN) + klo + r) * 64 + c * 4);
    }
    CPA_COMMIT();
    // ---- Q convert in-kernel (1 item/thread) ----
    {
        int r = tid >> 4, dq = tid & 15;
        float4 v = ((const float4*)Q)[((size_t)(bh * S_LEN) + q0 + r) * 16 + dq];
        float x0 = v.x * 0.125f, x1 = v.y * 0.125f, x2 = v.z * 0.125f, x3 = v.w * 0.125f;
        int ks = dq >> 2;
        int p0 = PERM((2 * dq) & 7), p1 = PERM((2 * dq + 1) & 7);
        uint32_t* qr2 = su + O_Q + r * SK;
        uint32_t g0 = pk(x0, x1), g1 = pk(x2, x3);
        int o0 = ks * 16 + ((p0 >> 1) << 2) + (p0 & 1);
        int o1 = ks * 16 + ((p1 >> 1) << 2) + (p1 & 1);
        qr2[o0] = g0; qr2[o0 + 2] = pkres(x0, x1, g0);
        qr2[o1] = g1; qr2[o1 + 2] = pkres(x2, x3, g1);
    }
    // ---- zero-fill attn outside the 320-wide strip ----
    {
        float* t0 = attn + (size_t)q0 * S_LEN;
        if (4 * tid + 3 < klo || 4 * tid >= klo + KW) {
            const float4 z4 = make_float4(0.f, 0.f, 0.f, 0.f);
            #pragma unroll 8
            for (int r = 0; r < TQ; ++r)
                ((float4*)(t0 + (size_t)r * S_LEN))[tid] = z4;
        }
    }
    CPA_WAIT0();
    __syncthreads();

    // ---- warp geometry + frag classes (all warp-uniform) ----
    const int qr = m * 16, nb = nw * 40;
    const int rbase = q0 + qr;
    const int glo = max(0, rbase - 127) - klo;
    const int ghi = min(S_LEN - 1, rbase + 15 + 127) - klo;
    bool alive[5], fullin[5];
    #pragma unroll
    for (int f = 0; f < 5; ++f) {
        int flo = klo + nb + 8 * f, fhi = flo + 7;
        alive[f]  = (fhi - klo >= glo) && (flo - klo <= ghi);
        fullin[f] = (flo >= rbase - 112) && (fhi <= rbase + 127) && (fhi <= khi);
    }

    // ---- GEMM1: C[32x320] = Qs . K^T (bf16 3-term, LDS.128 frags) ----
    float4 C[5];
    #pragma unroll
    for (int f = 0; f < 5; ++f) C[f] = make_float4(0.f, 0.f, 0.f, 0.f);

    #pragma unroll
    for (int ks = 0; ks < 4; ++ks) {
        uint4 qv0 = *(const uint4*)(su + O_Q + (qr + gid) * SK + ks * 16 + tig * 4);
        uint4 qv1 = *(const uint4*)(su + O_Q + (qr + gid + 8) * SK + ks * 16 + tig * 4);
        #pragma unroll
        for (int f = 0; f < 5; ++f) {
            if (!alive[f]) continue;
            uint4 kv = *(const uint4*)(su + O_K + (nb + 8 * f + gid) * SK + ks * 16 + tig * 4);
            mmabf(C[f], qv0.x, qv1.x, qv0.y, qv1.y, kv.x, kv.y);   // hh
            mmabf(C[f], qv0.z, qv1.z, qv0.w, qv1.w, kv.x, kv.y);   // lh
            mmabf(C[f], qv0.x, qv1.x, qv0.y, qv1.y, kv.z, kv.w);   // hl
        }
    }

    // ---- mask: full-in frags skip all per-element ALU ----
    const int r0g = rbase + gid;
    #pragma unroll
    for (int f = 0; f < 5; ++f) {
        if (fullin[f]) continue;
        if (!alive[f]) { C[f] = make_float4(-INFINITY, -INFINITY, -INFINITY, -INFINITY); continue; }
        int k0 = klo + nb + 8 * f + 2 * tig;
        bool v0 = (unsigned)(r0g     - k0     + WIN - 1) <= 2 * (WIN - 1) && k0     <= khi;
        bool v1 = (unsigned)(r0g     - k0 - 1 + WIN - 1) <= 2 * (WIN - 1) && k0 + 1 <= khi;
        bool v2 = (unsigned)(r0g + 8 - k0     + WIN - 1) <= 2 * (WIN - 1) && k0     <= khi;
        bool v3 = (unsigned)(r0g + 8 - k0 - 1 + WIN - 1) <= 2 * (WIN - 1) && k0 + 1 <= khi;
        C[f].x = v0 ? C[f].x : -INFINITY;
        C[f].y = v1 ? C[f].y : -INFINITY;
        C[f].z = v2 ? C[f].z : -INFINITY;
        C[f].w = v3 ? C[f].w : -INFINITY;
    }

    // ---- local row max ----
    float mr0 = -INFINITY, mr1 = -INFINITY;
    #pragma unroll
    for (int f = 0; f < 5; ++f) {
        mr0 = fmaxf(mr0, fmaxf(C[f].x, C[f].y));
        mr1 = fmaxf(mr1, fmaxf(C[f].z, C[f].w));
    }
    #pragma unroll
    for (int off = 1; off <= 2; off <<= 1) {
        mr0 = fmaxf(mr0, __shfl_xor_sync(0xffffffffu, mr0, off));
        mr1 = fmaxf(mr1, __shfl_xor_sync(0xffffffffu, mr1, off));
    }
    mr0 = fmaxf(mr0, -1e30f); mr1 = fmaxf(mr1, -1e30f);
    // ---- e = exp(c - mloc), kept in C; local sums ----
    float sr0 = 0.f, sr1 = 0.f;
    #pragma unroll
    for (int f = 0; f < 5; ++f) {
        C[f].x = __expf(C[f].x - mr0); C[f].y = __expf(C[f].y - mr0);
        C[f].z = __expf(C[f].z - mr1); C[f].w = __expf(C[f].w - mr1);
        sr0 += C[f].x + C[f].y;
        sr1 += C[f].z + C[f].w;
    }
    #pragma unroll
    for (int off = 1; off <= 2; off <<= 1) {
        sr0 += __shfl_xor_sync(0xffffffffu, sr0, off);
        sr1 += __shfl_xor_sync(0xffffffffu, sr1, off);
    }
    if (tig == 0) {
        sf[O_MS + nw * 32 + qr + gid]     = mr0;  sf[O_SS + nw * 32 + qr + gid]     = sr0;
        sf[O_MS + nw * 32 + qr + gid + 8] = mr1;  sf[O_SS + nw * 32 + qr + gid + 8] = sr1;
    }
    __syncthreads();   // K dead; stats visible

    // ---- Vt copy into K region via cp.async (overlaps softmax-const math) ----
    {
        int d = tid >> 3, c0 = tid & 7;
        size_t gb = (size_t)(bh * DH + d) * VROW + klo2 * 2;
        #pragma unroll
        for (int j = 0; j < 10; ++j)
            cpa16(sbase + (d * SV + (c0 + j * 8) * 4) * 4, d_Vt + gb + (c0 + j * 8) * 4);
        CPA_COMMIT();
    }

    // ---- global softmax constant per row ----
    float M0 = -INFINITY, M1 = -INFINITY;
    #pragma unroll
    for (int n2 = 0; n2 < 8; ++n2) {
        M0 = fmaxf(M0, sf[O_MS + n2 * 32 + qr + gid]);
        M1 = fmaxf(M1, sf[O_MS + n2 * 32 + qr + gid + 8]);
    }
    float S0 = 0.f, S1 = 0.f;
    #pragma unroll
    for (int n2 = 0; n2 < 8; ++n2) {
        S0 += sf[O_SS + n2 * 32 + qr + gid]     * __expf(sf[O_MS + n2 * 32 + qr + gid]     - M0);
        S1 += sf[O_SS + n2 * 32 + qr + gid + 8] * __expf(sf[O_MS + n2 * 32 + qr + gid + 8] - M1);
    }
    // p = e * exp(mloc - Cr), Cr = M + ln(S)
    const float sc0 = __expf(mr0 - M0 - __logf(S0));
    const float sc1 = __expf(mr1 - M1 - __logf(S1));
    CPA_WAIT0();
    __syncthreads();   // Vt ready

    // ---- p = e * sc; attn band stores ----
    #pragma unroll
    for (int f = 0; f < 5; ++f) {
        float p0 = C[f].x * sc0, p1 = C[f].y * sc0;
        float p2 = C[f].z * sc1, p3 = C[f].w * sc1;
        C[f] = make_float4(p0, p1, p2, p3);
        int k0 = klo + nb + 8 * f + 2 * tig;
        if (k0 < S_LEN) {
            *(float2*)(attn + (size_t)r0g       * S_LEN + k0) = make_float2(p0, p1);
            *(float2*)(attn + (size_t)(r0g + 8) * S_LEN + k0) = make_float2(p2, p3);
        }
    }

    // ---- GEMM2: ctx = P . V ----
    float4 acc[8];
    #pragma unroll
    for (int nt = 0; nt < 8; ++nt) acc[nt] = make_float4(0.f, 0.f, 0.f, 0.f);
    const int chunk0 = (nb - 8 * (nw & 1)) >> 4;
    if (!(nw & 1)) { G2STEP(0, 1, 0); G2STEP(2, 3, 1); G2STEP(4, 5, 2); }
    else           { G2STEP(-1, 0, 0); G2STEP(1, 2, 1); G2STEP(3, 4, 2); }
    __syncthreads();   // Vt dead

    // ---- combine 8 nw partials ----
    if (nw) {
        float4* sp = (float4*)sf + (m * 7 + nw - 1) * 256;
        #pragma unroll
        for (int nt = 0; nt < 8; ++nt) sp[nt * 32 + lane] = acc[nt];
    }
    __syncthreads();
    if (!nw) {
        #pragma unroll
        for (int s = 0; s < 7; ++s) {
            const float4* sp = (const float4*)sf + (m * 7 + s) * 256;
            #pragma unroll
            for (int nt = 0; nt < 8; ++nt) {
                float4 t = sp[nt * 32 + lane];
                acc[nt].x += t.x; acc[nt].y += t.y; acc[nt].z += t.z; acc[nt].w += t.w;
            }
        }
        float* cb = ctx_out + ((size_t)bh * S_LEN + q0 + qr) * DH;
        #pragma unroll
        for (int nt = 0; nt < 8; ++nt) {
            int d0 = nt * 8 + 2 * tig;
            *(float2*)(cb + gid * DH + d0)       = make_float2(acc[nt].x, acc[nt].y);
            *(float2*)(cb + (gid + 8) * DH + d0) = make_float2(acc[nt].z, acc[nt].w);
        }
    }
}

extern "C" void kernel_launch(void* const* d_in, const int* in_sizes, int n_in,
                              void* d_out, int out_size)
{
    const float* Q = (const float*)d_in[0];
    const float* K = (const float*)d_in[1];
    const float* V = (const float*)d_in[2];

    float* out  = (float*)d_out;
    float* ctx  = out;                                 // [B,H,S,D] first
    float* attn = out + (size_t)NB * NH * S_LEN * DH;  // then [B,H,S,S]

    prep_kernel<<<(NB * NH * S_LEN * 16) / 256, 256>>>(K, V);

    cudaFuncSetAttribute(band_attn_bf16,
                         cudaFuncAttributeMaxDynamicSharedMemorySize, SMEM_B);
    dim3 grid(S_LEN / TQ, NH, NB);
    band_attn_bf16<<<grid, NT, SMEM_B>>>(Q, K, V, ctx, attn);
}